// round 1
// baseline (speedup 1.0000x reference)
#include <cuda_runtime.h>
#include <cuda_bf16.h>
#include <mma.h>

using namespace nvcuda;

// Problem constants
#define Bn 2
#define Dm 256
#define Cc 64
#define Tt 1024
#define Hh 8
#define Ff 32
#define CT 65536           // Cc*Tt
#define E3 768             // 3*Dm
#define EPS 1e-5f
#define SCALE 0.1767766952966369f  // 1/sqrt(32)

// ---------------- scratch (device globals; no allocations allowed) ----------------
__device__ __nv_bfloat16 g_qkv[(size_t)Bn * E3 * CT];    // 201 MB
__device__ __nv_bfloat16 g_attn[(size_t)Bn * Dm * CT];   // 67 MB
__device__ float g_mu[Bn * Dm];
__device__ float g_rstd[Bn * Dm];
__device__ __nv_bfloat16 g_weff[(size_t)Bn * E3 * Dm];   // per-batch folded weights
__device__ float g_bias[Bn * E3];
__device__ __nv_bfloat16 g_wout[Dm * Dm];

// ---------------- K1: instance-norm stats (per (b,d) over 65536 elems) ----------------
__global__ __launch_bounds__(256) void stats_kernel(const float* __restrict__ x) {
    size_t base = (size_t)blockIdx.x * CT;
    const float4* p = (const float4*)(x + base);
    float s = 0.f, ss = 0.f;
    for (int i = threadIdx.x; i < CT / 4; i += 256) {
        float4 v = p[i];
        s += v.x + v.y + v.z + v.w;
        ss += v.x * v.x + v.y * v.y + v.z * v.z + v.w * v.w;
    }
    // block reduce
    __shared__ float rs[8], rss[8];
    for (int off = 16; off; off >>= 1) {
        s  += __shfl_down_sync(~0u, s, off);
        ss += __shfl_down_sync(~0u, ss, off);
    }
    int wid = threadIdx.x >> 5, lane = threadIdx.x & 31;
    if (lane == 0) { rs[wid] = s; rss[wid] = ss; }
    __syncthreads();
    if (threadIdx.x == 0) {
        float S = 0.f, SS = 0.f;
        for (int i = 0; i < 8; i++) { S += rs[i]; SS += rss[i]; }
        float mu = S / (float)CT;
        float var = SS / (float)CT - mu * mu;
        g_mu[blockIdx.x] = mu;
        g_rstd[blockIdx.x] = rsqrtf(var + EPS);
    }
}

// ---------------- K2: fold instance norm into weights ----------------
__global__ __launch_bounds__(256) void prep_weights(const float* __restrict__ in_w,
                                                    const float* __restrict__ in_b) {
    int be = blockIdx.x;           // b*768 + e
    int b = be / E3, e = be % E3;
    int d = threadIdx.x;
    float w = in_w[e * Dm + d];
    float r = g_rstd[b * Dm + d];
    float m = g_mu[b * Dm + d];
    float we = w * r;
    g_weff[(size_t)be * Dm + d] = __float2bfloat16(we);
    __shared__ float red[256];
    red[d] = we * m;
    __syncthreads();
    for (int s = 128; s > 0; s >>= 1) {
        if (d < s) red[d] += red[d + s];
        __syncthreads();
    }
    if (d == 0) g_bias[be] = in_b[e] - red[0];
}

__global__ __launch_bounds__(256) void conv_outw(const float* __restrict__ out_w) {
    int i = blockIdx.x * 256 + threadIdx.x;
    g_wout[i] = __float2bfloat16(out_w[i]);
}

// ---------------- K3: qkv GEMM  C[e,ct] = Weff[e,:] @ x[:,ct] + bias ----------------
// block tile 64(M) x 128(N), BK=32, 8 warps (2x4), warp tile 32x32 (2x2 wmma m16n16k16)
__global__ __launch_bounds__(256) void qkv_gemm(const float* __restrict__ x) {
    const int bx = blockIdx.x;   // ct tile (128)
    const int by = blockIdx.y;   // e tile (64)
    const int b  = blockIdx.z;

    __shared__ __align__(16) __nv_bfloat16 A_s[64][40];
    __shared__ __align__(16) __nv_bfloat16 B_s[32][136];
    __shared__ __align__(16) float stage[64][132];

    const int tid = threadIdx.x;
    const int w = tid >> 5;
    const int wm = w >> 2, wn = w & 3;

    wmma::fragment<wmma::accumulator, 16, 16, 16, float> acc[2][2];
    for (int i = 0; i < 2; i++)
        for (int j = 0; j < 2; j++) wmma::fill_fragment(acc[i][j], 0.0f);

    const __nv_bfloat16* Aptr = g_weff + (size_t)(b * E3 + by * 64) * Dm;
    const float* Bptr = x + (size_t)b * Dm * CT + (size_t)bx * 128;

    for (int k0 = 0; k0 < Dm; k0 += 32) {
        // load A: 64x32 bf16, one uint4 (8 bf16) per thread
        {
            int r = tid >> 2, c8 = (tid & 3) * 8;
            const uint4* src = (const uint4*)(Aptr + (size_t)r * Dm + k0 + c8);
            *(uint4*)(&A_s[r][c8]) = *src;
        }
        // load B: 32x128 fp32 -> bf16, 4 float4 per thread
        #pragma unroll
        for (int it = 0; it < 4; it++) {
            int idx = tid + it * 256;
            int r = idx >> 5, c4 = (idx & 31) * 4;
            float4 v = *(const float4*)(Bptr + (size_t)(k0 + r) * CT + c4);
            B_s[r][c4 + 0] = __float2bfloat16(v.x);
            B_s[r][c4 + 1] = __float2bfloat16(v.y);
            B_s[r][c4 + 2] = __float2bfloat16(v.z);
            B_s[r][c4 + 3] = __float2bfloat16(v.w);
        }
        __syncthreads();
        #pragma unroll
        for (int kk = 0; kk < 32; kk += 16) {
            wmma::fragment<wmma::matrix_a, 16, 16, 16, __nv_bfloat16, wmma::row_major> af[2];
            wmma::fragment<wmma::matrix_b, 16, 16, 16, __nv_bfloat16, wmma::row_major> bf[2];
            wmma::load_matrix_sync(af[0], &A_s[wm * 32][kk], 40);
            wmma::load_matrix_sync(af[1], &A_s[wm * 32 + 16][kk], 40);
            wmma::load_matrix_sync(bf[0], &B_s[kk][wn * 32], 136);
            wmma::load_matrix_sync(bf[1], &B_s[kk][wn * 32 + 16], 136);
            #pragma unroll
            for (int i = 0; i < 2; i++)
                #pragma unroll
                for (int j = 0; j < 2; j++)
                    wmma::mma_sync(acc[i][j], af[i], bf[j], acc[i][j]);
        }
        __syncthreads();
    }

    // epilogue: stage -> +bias -> bf16 global
    for (int i = 0; i < 2; i++)
        for (int j = 0; j < 2; j++)
            wmma::store_matrix_sync(&stage[wm * 32 + i * 16][wn * 32 + j * 16],
                                    acc[i][j], 132, wmma::mem_row_major);
    __syncthreads();
    for (int idx = tid; idx < 64 * 128; idx += 256) {
        int r = idx >> 7, cc = idx & 127;
        int e = by * 64 + r;
        float v = stage[r][cc] + g_bias[b * E3 + e];
        g_qkv[(size_t)(b * E3 + e) * CT + (size_t)bx * 128 + cc] = __float2bfloat16(v);
    }
}

// ---------------- K4: fused attention per (n=b*c, h) ----------------
__global__ __launch_bounds__(256) void attn_kernel() {
    const int bid = blockIdx.x;
    const int h = bid & 7;
    const int n = bid >> 3;
    const int b = n >> 6;
    const int c = n & 63;
    const int tid = threadIdx.x;

    const size_t cof = (size_t)c * Tt;
    const __nv_bfloat16* gq = g_qkv + (size_t)(b * E3 + h * Ff) * CT + cof;
    const __nv_bfloat16* gk = gq + (size_t)Dm * CT;
    const __nv_bfloat16* gv = gq + (size_t)(2 * Dm) * CT;
    __nv_bfloat16* gout = g_attn + (size_t)(b * Dm + h * Ff) * CT + cof;

    __shared__ float ks[32][129];
    __shared__ float vs[32][129];
    __shared__ float ctx_s[32][33];
    __shared__ float rmax[32], rinv[32];

    // Phase 1: online softmax stats for k rows (over t)
    {
        int wid = tid >> 5, lane = tid & 31;
        for (int fi = 0; fi < 4; fi++) {
            int fk = wid * 4 + fi;
            const __nv_bfloat16* kp = gk + (size_t)fk * CT;
            float m = -1e30f, s = 0.f;
            for (int t = lane; t < Tt; t += 32) {
                float v = __bfloat162float(kp[t]);
                float nm = fmaxf(m, v);
                s = s * __expf(m - nm) + __expf(v - nm);
                m = nm;
            }
            for (int off = 16; off; off >>= 1) {
                float om = __shfl_down_sync(~0u, m, off);
                float os = __shfl_down_sync(~0u, s, off);
                float nm = fmaxf(m, om);
                s = s * __expf(m - nm) + os * __expf(om - nm);
                m = nm;
            }
            if (lane == 0) { rmax[fk] = m; rinv[fk] = 1.0f / s; }
        }
    }
    __syncthreads();

    // Phase 2: ctx[fk][fv] = sum_t ksoft[fk,t] * v[fv,t]/T
    float cx00 = 0.f, cx01 = 0.f, cx10 = 0.f, cx11 = 0.f;
    const int ti = tid >> 4, tj = tid & 15;
    for (int tc = 0; tc < Tt; tc += 128) {
        __syncthreads();
        for (int idx = tid; idx < 4096; idx += 256) {
            int f = idx >> 7, tt = idx & 127;
            float kv = __bfloat162float(gk[(size_t)f * CT + tc + tt]);
            ks[f][tt] = __expf(kv - rmax[f]) * rinv[f];
            float vv = __bfloat162float(gv[(size_t)f * CT + tc + tt]);
            vs[f][tt] = vv * (1.0f / (float)Tt);
        }
        __syncthreads();
        #pragma unroll 8
        for (int tt = 0; tt < 128; tt++) {
            float a0 = ks[ti][tt], a1 = ks[ti + 16][tt];
            float b0 = vs[tj][tt], b1 = vs[tj + 16][tt];
            cx00 += a0 * b0; cx01 += a0 * b1;
            cx10 += a1 * b0; cx11 += a1 * b1;
        }
    }
    __syncthreads();
    ctx_s[ti][tj]           = cx00;
    ctx_s[ti][tj + 16]      = cx01;
    ctx_s[ti + 16][tj]      = cx10;
    ctx_s[ti + 16][tj + 16] = cx11;
    __syncthreads();

    // Phase 3: q column-softmax (over f) * scale, then out = ctx^T @ qs
    for (int tc = 0; tc < Tt; tc += 128) {
        __syncthreads();
        for (int idx = tid; idx < 4096; idx += 256) {
            int f = idx >> 7, tt = idx & 127;
            ks[f][tt] = __bfloat162float(gq[(size_t)f * CT + tc + tt]);
        }
        __syncthreads();
        if (tid < 128) {
            int tt = tid;
            float m = -1e30f;
            #pragma unroll
            for (int f = 0; f < 32; f++) m = fmaxf(m, ks[f][tt]);
            float s = 0.f;
            #pragma unroll
            for (int f = 0; f < 32; f++) s += __expf(ks[f][tt] - m);
            float inv = SCALE / s;
            #pragma unroll
            for (int f = 0; f < 32; f++) ks[f][tt] = __expf(ks[f][tt] - m) * inv;
        }
        __syncthreads();
        for (int idx = tid; idx < 4096; idx += 256) {
            int fv = idx >> 7, tt = idx & 127;
            float acc = 0.f;
            #pragma unroll
            for (int fk = 0; fk < 32; fk++) acc += ctx_s[fk][fv] * ks[fk][tt];
            gout[(size_t)fv * CT + tc + tt] = __float2bfloat16(acc);
        }
    }
}

// ---------------- K5: out projection + bias + residual ----------------
__global__ __launch_bounds__(256) void outproj_gemm(const float* __restrict__ x,
                                                    const float* __restrict__ out_b,
                                                    float* __restrict__ out) {
    const int bx = blockIdx.x;   // ct tile (128)
    const int by = blockIdx.y;   // e tile (64), 4 tiles
    const int b  = blockIdx.z;

    __shared__ __align__(16) __nv_bfloat16 A_s[64][40];
    __shared__ __align__(16) __nv_bfloat16 B_s[32][136];
    __shared__ __align__(16) float stage[64][132];

    const int tid = threadIdx.x;
    const int w = tid >> 5;
    const int wm = w >> 2, wn = w & 3;

    wmma::fragment<wmma::accumulator, 16, 16, 16, float> acc[2][2];
    for (int i = 0; i < 2; i++)
        for (int j = 0; j < 2; j++) wmma::fill_fragment(acc[i][j], 0.0f);

    const __nv_bfloat16* Aptr = g_wout + (size_t)(by * 64) * Dm;
    const __nv_bfloat16* Bptr = g_attn + (size_t)b * Dm * CT + (size_t)bx * 128;

    for (int k0 = 0; k0 < Dm; k0 += 32) {
        {
            int r = tid >> 2, c8 = (tid & 3) * 8;
            const uint4* src = (const uint4*)(Aptr + (size_t)r * Dm + k0 + c8);
            *(uint4*)(&A_s[r][c8]) = *src;
        }
        #pragma unroll
        for (int it = 0; it < 2; it++) {
            int idx = tid + it * 256;
            int r = idx >> 4, c8 = (idx & 15) * 8;
            const uint4* src = (const uint4*)(Bptr + (size_t)(k0 + r) * CT + c8);
            *(uint4*)(&B_s[r][c8]) = *src;
        }
        __syncthreads();
        #pragma unroll
        for (int kk = 0; kk < 32; kk += 16) {
            wmma::fragment<wmma::matrix_a, 16, 16, 16, __nv_bfloat16, wmma::row_major> af[2];
            wmma::fragment<wmma::matrix_b, 16, 16, 16, __nv_bfloat16, wmma::row_major> bf[2];
            wmma::load_matrix_sync(af[0], &A_s[wm * 32][kk], 40);
            wmma::load_matrix_sync(af[1], &A_s[wm * 32 + 16][kk], 40);
            wmma::load_matrix_sync(bf[0], &B_s[kk][wn * 32], 136);
            wmma::load_matrix_sync(bf[1], &B_s[kk][wn * 32 + 16], 136);
            #pragma unroll
            for (int i = 0; i < 2; i++)
                #pragma unroll
                for (int j = 0; j < 2; j++)
                    wmma::mma_sync(acc[i][j], af[i], bf[j], acc[i][j]);
        }
        __syncthreads();
    }

    for (int i = 0; i < 2; i++)
        for (int j = 0; j < 2; j++)
            wmma::store_matrix_sync(&stage[wm * 32 + i * 16][wn * 32 + j * 16],
                                    acc[i][j], 132, wmma::mem_row_major);
    __syncthreads();
    for (int idx = tid; idx < 64 * 128; idx += 256) {
        int r = idx >> 7, cc = idx & 127;
        int e = by * 64 + r;
        size_t gi = (size_t)(b * Dm + e) * CT + (size_t)bx * 128 + cc;
        out[gi] = stage[r][cc] + out_b[e] + x[gi];
    }
}

// ---------------- launch ----------------
extern "C" void kernel_launch(void* const* d_in, const int* in_sizes, int n_in,
                              void* d_out, int out_size) {
    const float* x     = (const float*)d_in[0];
    const float* in_w  = (const float*)d_in[1];
    const float* in_b  = (const float*)d_in[2];
    const float* out_w = (const float*)d_in[3];
    const float* out_b = (const float*)d_in[4];
    float* out = (float*)d_out;

    stats_kernel<<<Bn * Dm, 256>>>(x);
    prep_weights<<<Bn * E3, 256>>>(in_w, in_b);
    conv_outw<<<Dm * Dm / 256, 256>>>(out_w);
    qkv_gemm<<<dim3(CT / 128, E3 / 64, Bn), 256>>>(x);
    attn_kernel<<<Bn * Cc * Hh, 256>>>();
    outproj_gemm<<<dim3(CT / 128, Dm / 64, Bn), 256>>>(x, out_b, out);
}

// round 4
// speedup vs baseline: 1.5253x; 1.5253x over previous
#include <cstdint>
#include <cuda_runtime.h>
#include <cuda_bf16.h>
#include <mma.h>

using namespace nvcuda;

// Problem constants
#define Bn 2
#define Dm 256
#define Cc 64
#define Tt 1024
#define Hh 8
#define Ff 32
#define CT 65536           // Cc*Tt
#define E3 768             // 3*Dm
#define EPS 1e-5f
#define SCALE 0.1767766952966369f  // 1/sqrt(32)

// ---------------- scratch (16B+ aligned for vector/cp.async access) ----------------
__device__ __align__(128) __nv_bfloat16 g_qkv[(size_t)Bn * E3 * CT];    // 201 MB
__device__ __align__(128) __nv_bfloat16 g_attn[(size_t)Bn * Dm * CT];   // 67 MB
__device__ __align__(128) __nv_bfloat16 g_xbf[(size_t)Bn * Dm * CT];    // 67 MB
__device__ float g_mu[Bn * Dm];
__device__ float g_rstd[Bn * Dm];
__device__ __align__(128) __nv_bfloat16 g_weff[(size_t)Bn * E3 * Dm];
__device__ float g_bias[Bn * E3];
__device__ __align__(128) __nv_bfloat16 g_wout[Dm * Dm];

// ---------------- cp.async helpers ----------------
__device__ __forceinline__ void cp16(void* smem, const void* gmem) {
    unsigned s = (unsigned)__cvta_generic_to_shared(smem);
    asm volatile("cp.async.cg.shared.global [%0], [%1], 16;\n" :: "r"(s), "l"(gmem));
}
#define CP_COMMIT() asm volatile("cp.async.commit_group;\n")
#define CP_WAIT1()  asm volatile("cp.async.wait_group 1;\n")
#define CP_WAIT0()  asm volatile("cp.async.wait_group 0;\n")

// ---------------- K1: stats + convert x to bf16 ----------------
__global__ __launch_bounds__(256) void stats_cvt(const float* __restrict__ x) {
    size_t base = (size_t)blockIdx.x * CT;
    const float4* p = (const float4*)(x + base);
    __nv_bfloat16* ob = g_xbf + base;
    float s = 0.f, ss = 0.f;
    for (int i = threadIdx.x; i < CT / 4; i += 256) {
        float4 v = p[i];
        s += v.x + v.y + v.z + v.w;
        ss += v.x * v.x + v.y * v.y + v.z * v.z + v.w * v.w;
        union { uint2 u; __nv_bfloat162 h[2]; } pk;
        pk.h[0] = __floats2bfloat162_rn(v.x, v.y);
        pk.h[1] = __floats2bfloat162_rn(v.z, v.w);
        *(uint2*)(ob + (size_t)i * 4) = pk.u;
    }
    __shared__ float rs[8], rss[8];
    for (int off = 16; off; off >>= 1) {
        s  += __shfl_down_sync(~0u, s, off);
        ss += __shfl_down_sync(~0u, ss, off);
    }
    int wid = threadIdx.x >> 5, lane = threadIdx.x & 31;
    if (lane == 0) { rs[wid] = s; rss[wid] = ss; }
    __syncthreads();
    if (threadIdx.x == 0) {
        float S = 0.f, SS = 0.f;
        for (int i = 0; i < 8; i++) { S += rs[i]; SS += rss[i]; }
        float mu = S / (float)CT;
        float var = SS / (float)CT - mu * mu;
        g_mu[blockIdx.x] = mu;
        g_rstd[blockIdx.x] = rsqrtf(var + EPS);
    }
}

// ---------------- K2: fold instance norm into weights ----------------
__global__ __launch_bounds__(256) void prep_weights(const float* __restrict__ in_w,
                                                    const float* __restrict__ in_b) {
    int be = blockIdx.x;
    int b = be / E3, e = be % E3;
    int d = threadIdx.x;
    float w = in_w[e * Dm + d];
    float r = g_rstd[b * Dm + d];
    float m = g_mu[b * Dm + d];
    float we = w * r;
    g_weff[(size_t)be * Dm + d] = __float2bfloat16(we);
    __shared__ float red[256];
    red[d] = we * m;
    __syncthreads();
    for (int s = 128; s > 0; s >>= 1) {
        if (d < s) red[d] += red[d + s];
        __syncthreads();
    }
    if (d == 0) g_bias[be] = in_b[e] - red[0];
}

__global__ __launch_bounds__(256) void conv_outw(const float* __restrict__ out_w) {
    int i = blockIdx.x * 256 + threadIdx.x;
    g_wout[i] = __float2bfloat16(out_w[i]);
}

// ---------------- K3: qkv GEMM 128x128 tile, cp.async double buffered ----------------
__global__ __launch_bounds__(256) void qkv_gemm() {
    const int bx = blockIdx.x;   // ct tile (128)
    const int by = blockIdx.y;   // e tile (128), 6 tiles
    const int b  = blockIdx.z;

    __shared__ __align__(16) char smem_raw[2 * 128 * 40 * 2 + 2 * 32 * 136 * 2];
    typedef __nv_bfloat16 bf;
    bf (*A_s)[128][40]  = (bf(*)[128][40])smem_raw;
    bf (*B_s)[32][136]  = (bf(*)[32][136])(smem_raw + 2 * 128 * 40 * 2);
    float (*stage)[132] = (float(*)[132])smem_raw;   // reused in epilogue

    const int tid = threadIdx.x;
    const int w = tid >> 5;
    const int wm = w >> 2, wn = w & 3;

    const bf* Aptr = g_weff + (size_t)(b * E3 + by * 128) * Dm;
    const bf* Bptr = g_xbf + (size_t)b * Dm * CT + (size_t)bx * 128;

    wmma::fragment<wmma::accumulator, 16, 16, 16, float> acc[4][2];
    #pragma unroll
    for (int i = 0; i < 4; i++)
        #pragma unroll
        for (int j = 0; j < 2; j++) wmma::fill_fragment(acc[i][j], 0.0f);

    auto loadA = [&](int s, int k0) {
        #pragma unroll
        for (int it = 0; it < 2; it++) {
            int idx = tid + it * 256;
            int r = idx >> 2, c8 = (idx & 3) * 8;
            cp16(&A_s[s][r][c8], Aptr + (size_t)r * Dm + k0 + c8);
        }
    };
    auto loadB = [&](int s, int k0) {
        #pragma unroll
        for (int it = 0; it < 2; it++) {
            int idx = tid + it * 256;
            int r = idx >> 4, c8 = (idx & 15) * 8;
            cp16(&B_s[s][r][c8], Bptr + (size_t)(k0 + r) * CT + c8);
        }
    };

    loadA(0, 0); loadB(0, 0); CP_COMMIT();

    for (int ks = 0; ks < 8; ks++) {
        int cur = ks & 1;
        if (ks < 7) {
            loadA(cur ^ 1, (ks + 1) * 32);
            loadB(cur ^ 1, (ks + 1) * 32);
            CP_COMMIT();
            CP_WAIT1();
        } else {
            CP_WAIT0();
        }
        __syncthreads();
        #pragma unroll
        for (int kk = 0; kk < 32; kk += 16) {
            wmma::fragment<wmma::matrix_a, 16, 16, 16, bf, wmma::row_major> af[4];
            wmma::fragment<wmma::matrix_b, 16, 16, 16, bf, wmma::row_major> bfr[2];
            #pragma unroll
            for (int i = 0; i < 4; i++)
                wmma::load_matrix_sync(af[i], &A_s[cur][wm * 64 + i * 16][kk], 40);
            #pragma unroll
            for (int j = 0; j < 2; j++)
                wmma::load_matrix_sync(bfr[j], &B_s[cur][kk][wn * 32 + j * 16], 136);
            #pragma unroll
            for (int i = 0; i < 4; i++)
                #pragma unroll
                for (int j = 0; j < 2; j++)
                    wmma::mma_sync(acc[i][j], af[i], bfr[j], acc[i][j]);
        }
        __syncthreads();
    }

    // epilogue in 2 chunks of 64 rows
    #pragma unroll
    for (int ch = 0; ch < 2; ch++) {
        if (wm == ch) {
            #pragma unroll
            for (int i = 0; i < 4; i++)
                #pragma unroll
                for (int j = 0; j < 2; j++)
                    wmma::store_matrix_sync(&stage[i * 16][wn * 32 + j * 16],
                                            acc[i][j], 132, wmma::mem_row_major);
        }
        __syncthreads();
        for (int idx = tid; idx < 64 * 128; idx += 256) {
            int r = idx >> 7, cc = idx & 127;
            int e = by * 128 + ch * 64 + r;
            float v = stage[r][cc] + g_bias[b * E3 + e];
            g_qkv[(size_t)(b * E3 + e) * CT + (size_t)bx * 128 + cc] = __float2bfloat16(v);
        }
        __syncthreads();
    }
}

// ---------------- K4: fused attention per (n=b*c, h), tensor cores ----------------
__global__ __launch_bounds__(256) void attn_kernel() {
    const int bid = blockIdx.x;
    const int h = bid & 7;
    const int n = bid >> 3;
    const int b = n >> 6;
    const int c = n & 63;
    const int tid = threadIdx.x;
    const int w = tid >> 5;

    const size_t cof = (size_t)c * Tt;
    const __nv_bfloat16* gq = g_qkv + (size_t)(b * E3 + h * Ff) * CT + cof;
    const __nv_bfloat16* gk = gq + (size_t)Dm * CT;
    const __nv_bfloat16* gv = gq + (size_t)(2 * Dm) * CT;
    __nv_bfloat16* gout = g_attn + (size_t)(b * Dm + h * Ff) * CT + cof;

    __shared__ __align__(16) __nv_bfloat16 ks[32][136];
    __shared__ __align__(16) __nv_bfloat16 vs[32][136];
    __shared__ __align__(16) float stage[32][148];    // 4 tiles at col q*36 (16B-aligned)
    __shared__ __align__(16) __nv_bfloat16 ctxb[32][40];
    __shared__ float rmax[32], rinv[32];

    // Phase 1: k-row softmax stats (over t)
    {
        int lane = tid & 31;
        for (int fi = 0; fi < 4; fi++) {
            int fk = w * 4 + fi;
            const __nv_bfloat16* kp = gk + (size_t)fk * CT;
            float m = -1e30f, s = 0.f;
            for (int t = lane; t < Tt; t += 32) {
                float v = __bfloat162float(kp[t]);
                float nm = fmaxf(m, v);
                s = s * __expf(m - nm) + __expf(v - nm);
                m = nm;
            }
            for (int off = 16; off; off >>= 1) {
                float om = __shfl_down_sync(~0u, m, off);
                float os = __shfl_down_sync(~0u, s, off);
                float nm = fmaxf(m, om);
                s = s * __expf(m - nm) + os * __expf(om - nm);
                m = nm;
            }
            if (lane == 0) { rmax[fk] = m; rinv[fk] = 1.0f / s; }
        }
    }
    __syncthreads();

    // Phase 2: ctx[fk][fv] = sum_t ksoft[fk,t]*v[fv,t]/T
    wmma::fragment<wmma::accumulator, 16, 16, 16, float> cacc[2][2];
    #pragma unroll
    for (int i = 0; i < 2; i++)
        #pragma unroll
        for (int j = 0; j < 2; j++) wmma::fill_fragment(cacc[i][j], 0.0f);

    for (int tc = 0; tc < Tt; tc += 128) {
        __syncthreads();
        for (int idx = tid; idx < 512; idx += 256) {
            int f = idx >> 4, t8 = (idx & 15) * 8;
            const __nv_bfloat162* kp = (const __nv_bfloat162*)(gk + (size_t)f * CT + tc + t8);
            const __nv_bfloat162* vp = (const __nv_bfloat162*)(gv + (size_t)f * CT + tc + t8);
            float mm = rmax[f], iv = rinv[f];
            #pragma unroll
            for (int u = 0; u < 4; u++) {
                float2 kf = __bfloat1622float2(kp[u]);
                float2 vf = __bfloat1622float2(vp[u]);
                ks[f][t8 + 2 * u]     = __float2bfloat16(__expf(kf.x - mm) * iv);
                ks[f][t8 + 2 * u + 1] = __float2bfloat16(__expf(kf.y - mm) * iv);
                vs[f][t8 + 2 * u]     = __float2bfloat16(vf.x * (1.0f / 1024.0f));
                vs[f][t8 + 2 * u + 1] = __float2bfloat16(vf.y * (1.0f / 1024.0f));
            }
        }
        __syncthreads();
        wmma::fragment<wmma::matrix_a, 16, 16, 16, __nv_bfloat16, wmma::row_major> af;
        wmma::fragment<wmma::matrix_b, 16, 16, 16, __nv_bfloat16, wmma::col_major> bfr;
        #pragma unroll
        for (int i = 0; i < 2; i++) {
            wmma::load_matrix_sync(af, &ks[i * 16][w * 16], 136);
            #pragma unroll
            for (int j = 0; j < 2; j++) {
                wmma::load_matrix_sync(bfr, &vs[j * 16][w * 16], 136);
                wmma::mma_sync(cacc[i][j], af, bfr, cacc[i][j]);
            }
        }
    }

    // cross-warp reduction of 8 partial ctx tiles (tiles at stage[:, q*36..])
    auto storeP = [&](int q) {
        #pragma unroll
        for (int i = 0; i < 2; i++)
            #pragma unroll
            for (int j = 0; j < 2; j++)
                wmma::store_matrix_sync(&stage[i * 16][q * 36 + j * 16],
                                        cacc[i][j], 148, wmma::mem_row_major);
    };
    auto addP = [&](int q) {
        wmma::fragment<wmma::accumulator, 16, 16, 16, float> tmp;
        #pragma unroll
        for (int i = 0; i < 2; i++)
            #pragma unroll
            for (int j = 0; j < 2; j++) {
                wmma::load_matrix_sync(tmp, &stage[i * 16][q * 36 + j * 16],
                                       148, wmma::mem_row_major);
                for (int e = 0; e < tmp.num_elements; e++) cacc[i][j].x[e] += tmp.x[e];
            }
    };
    __syncthreads();
    if (w >= 4) storeP(w - 4);
    __syncthreads();
    if (w < 4) addP(w);
    __syncthreads();
    if (w == 2 || w == 3) storeP(w - 2);
    __syncthreads();
    if (w < 2) addP(w);
    __syncthreads();
    if (w == 1) storeP(0);
    __syncthreads();
    if (w == 0) { addP(0); storeP(0); }    // final ctx fp32 at stage[fk][fv]
    __syncthreads();
    for (int idx = tid; idx < 1024; idx += 256) {
        int fk = idx >> 5, fv = idx & 31;
        ctxb[fk][fv] = __float2bfloat16(stage[fk][fv]);
    }
    __syncthreads();

    // Phase 3: out[fv][t] = sum_fk ctx[fk][fv] * qsoft[fk][t]*scale
    const int mi = w >> 2;         // 0..1
    const int jb = (w & 3) * 2;    // N tile base
    for (int tc = 0; tc < Tt; tc += 128) {
        __syncthreads();
        for (int idx = tid; idx < 512; idx += 256) {
            int f = idx >> 4, t8 = (idx & 15) * 8;
            *(uint4*)&ks[f][t8] = *(const uint4*)(gq + (size_t)f * CT + tc + t8);
        }
        __syncthreads();
        if (tid < 128) {
            int tt = tid;
            float m = -1e30f;
            #pragma unroll
            for (int f = 0; f < 32; f++) m = fmaxf(m, __bfloat162float(ks[f][tt]));
            float s = 0.f;
            float ex[32];
            #pragma unroll
            for (int f = 0; f < 32; f++) {
                ex[f] = __expf(__bfloat162float(ks[f][tt]) - m);
                s += ex[f];
            }
            float inv = SCALE / s;
            #pragma unroll
            for (int f = 0; f < 32; f++) ks[f][tt] = __float2bfloat16(ex[f] * inv);
        }
        __syncthreads();
        wmma::fragment<wmma::accumulator, 16, 16, 16, float> o[2];
        #pragma unroll
        for (int jj = 0; jj < 2; jj++) wmma::fill_fragment(o[jj], 0.0f);
        #pragma unroll
        for (int kk = 0; kk < 2; kk++) {
            wmma::fragment<wmma::matrix_a, 16, 16, 16, __nv_bfloat16, wmma::col_major> af;
            wmma::load_matrix_sync(af, &ctxb[kk * 16][mi * 16], 40);
            #pragma unroll
            for (int jj = 0; jj < 2; jj++) {
                wmma::fragment<wmma::matrix_b, 16, 16, 16, __nv_bfloat16, wmma::row_major> bfr;
                wmma::load_matrix_sync(bfr, &ks[kk * 16][(jb + jj) * 16], 136);
                wmma::mma_sync(o[jj], af, bfr, o[jj]);
            }
        }
        #pragma unroll
        for (int jj = 0; jj < 2; jj++)
            wmma::store_matrix_sync(&stage[mi * 16][(jb + jj) * 16], o[jj],
                                    148, wmma::mem_row_major);
        __syncthreads();
        for (int idx = tid; idx < 4096; idx += 256) {
            int fv = idx >> 7, tt = idx & 127;
            gout[(size_t)fv * CT + tc + tt] = __float2bfloat16(stage[fv][tt]);
        }
    }
}

// ---------------- K5: out projection + bias + residual ----------------
__global__ __launch_bounds__(256) void outproj_gemm(const float* __restrict__ x,
                                                    const float* __restrict__ out_b,
                                                    float* __restrict__ out) {
    const int bx = blockIdx.x;
    const int by = blockIdx.y;
    const int b  = blockIdx.z;

    __shared__ __align__(16) char smem_raw[2 * 128 * 40 * 2 + 2 * 32 * 136 * 2];
    typedef __nv_bfloat16 bf;
    bf (*A_s)[128][40]  = (bf(*)[128][40])smem_raw;
    bf (*B_s)[32][136]  = (bf(*)[32][136])(smem_raw + 2 * 128 * 40 * 2);
    float (*stage)[132] = (float(*)[132])smem_raw;

    const int tid = threadIdx.x;
    const int w = tid >> 5;
    const int wm = w >> 2, wn = w & 3;

    const bf* Aptr = g_wout + (size_t)(by * 128) * Dm;
    const bf* Bptr = g_attn + (size_t)b * Dm * CT + (size_t)bx * 128;

    wmma::fragment<wmma::accumulator, 16, 16, 16, float> acc[4][2];
    #pragma unroll
    for (int i = 0; i < 4; i++)
        #pragma unroll
        for (int j = 0; j < 2; j++) wmma::fill_fragment(acc[i][j], 0.0f);

    auto loadA = [&](int s, int k0) {
        #pragma unroll
        for (int it = 0; it < 2; it++) {
            int idx = tid + it * 256;
            int r = idx >> 2, c8 = (idx & 3) * 8;
            cp16(&A_s[s][r][c8], Aptr + (size_t)r * Dm + k0 + c8);
        }
    };
    auto loadB = [&](int s, int k0) {
        #pragma unroll
        for (int it = 0; it < 2; it++) {
            int idx = tid + it * 256;
            int r = idx >> 4, c8 = (idx & 15) * 8;
            cp16(&B_s[s][r][c8], Bptr + (size_t)(k0 + r) * CT + c8);
        }
    };

    loadA(0, 0); loadB(0, 0); CP_COMMIT();

    for (int ks = 0; ks < 8; ks++) {
        int cur = ks & 1;
        if (ks < 7) {
            loadA(cur ^ 1, (ks + 1) * 32);
            loadB(cur ^ 1, (ks + 1) * 32);
            CP_COMMIT();
            CP_WAIT1();
        } else {
            CP_WAIT0();
        }
        __syncthreads();
        #pragma unroll
        for (int kk = 0; kk < 32; kk += 16) {
            wmma::fragment<wmma::matrix_a, 16, 16, 16, bf, wmma::row_major> af[4];
            wmma::fragment<wmma::matrix_b, 16, 16, 16, bf, wmma::row_major> bfr[2];
            #pragma unroll
            for (int i = 0; i < 4; i++)
                wmma::load_matrix_sync(af[i], &A_s[cur][wm * 64 + i * 16][kk], 40);
            #pragma unroll
            for (int j = 0; j < 2; j++)
                wmma::load_matrix_sync(bfr[j], &B_s[cur][kk][wn * 32 + j * 16], 136);
            #pragma unroll
            for (int i = 0; i < 4; i++)
                #pragma unroll
                for (int j = 0; j < 2; j++)
                    wmma::mma_sync(acc[i][j], af[i], bfr[j], acc[i][j]);
        }
        __syncthreads();
    }

    #pragma unroll
    for (int ch = 0; ch < 2; ch++) {
        if (wm == ch) {
            #pragma unroll
            for (int i = 0; i < 4; i++)
                #pragma unroll
                for (int j = 0; j < 2; j++)
                    wmma::store_matrix_sync(&stage[i * 16][wn * 32 + j * 16],
                                            acc[i][j], 132, wmma::mem_row_major);
        }
        __syncthreads();
        for (int idx = tid; idx < 64 * 128; idx += 256) {
            int r = idx >> 7, cc = idx & 127;
            int e = by * 128 + ch * 64 + r;
            size_t gi = (size_t)(b * Dm + e) * CT + (size_t)bx * 128 + cc;
            out[gi] = stage[r][cc] + out_b[e] + x[gi];
        }
        __syncthreads();
    }
}

// ---------------- launch ----------------
extern "C" void kernel_launch(void* const* d_in, const int* in_sizes, int n_in,
                              void* d_out, int out_size) {
    const float* x     = (const float*)d_in[0];
    const float* in_w  = (const float*)d_in[1];
    const float* in_b  = (const float*)d_in[2];
    const float* out_w = (const float*)d_in[3];
    const float* out_b = (const float*)d_in[4];
    float* out = (float*)d_out;

    stats_cvt<<<Bn * Dm, 256>>>(x);
    prep_weights<<<Bn * E3, 256>>>(in_w, in_b);
    conv_outw<<<Dm * Dm / 256, 256>>>(out_w);
    qkv_gemm<<<dim3(CT / 128, E3 / 128, Bn), 256>>>();
    attn_kernel<<<Bn * Cc * Hh, 256>>>();
    outproj_gemm<<<dim3(CT / 128, Dm / 128, Bn), 256>>>(x, out_b, out);
}